// round 7
// baseline (speedup 1.0000x reference)
#include <cuda_runtime.h>
#include <cstdint>

// ---------------------------------------------------------------------------
// DInPBlock: invo1 (32->64, s2) -> 5 dilated involutions -> concat -> bn+prelu
// Shapes: x (8,32,256,256) f32 ; out (8,320,128,128) f32
// f32x2 packed-FMA version (Blackwell FFMA2 via PTX fma.rn.f32x2)
// ---------------------------------------------------------------------------

#define NBATCH 8
typedef unsigned long long u64t;

#define FMA2(d, a, b, c) \
    asm("fma.rn.f32x2 %0, %1, %2, %3;" : "=l"(d) : "l"(a), "l"(b), "l"(c))
#define PACK2(d, lo, hi) \
    asm("mov.b64 %0, {%1, %2};" : "=l"(d) : "f"(lo), "f"(hi))
#define UNPACK2(lo, hi, s) \
    asm("mov.b64 {%0, %1}, %2;" : "=f"(lo), "=f"(hi) : "l"(s))

__device__ float g_xi[(size_t)NBATCH * 64 * 256 * 256];   // 134 MB
__device__ float g_kmap1[(size_t)NBATCH * 9 * 128 * 128];
__device__ float g_o1[(size_t)NBATCH * 64 * 128 * 128];   // 33.5 MB (L2-resident)

// ---------------------------------------------------------------------------
// K1: xi = conv1x1(x, w1_init)  (8,32,256,256) -> (8,64,256,256)
// 256 threads = 128 pixels x 2 halves; each thread 32 outputs (16 f32x2)
// ---------------------------------------------------------------------------
__global__ __launch_bounds__(256) void k_xi(const float* __restrict__ x,
                                            const float* __restrict__ w) {
    __shared__ float xs[32 * 128];  // xs[c*128+p]
    __shared__ float ws[32 * 64];   // ws[c*64+o] = w[o*32+c]
    const int tid = threadIdx.x;
    const int pbase = blockIdx.x * 128;
    const int b = pbase >> 16;
    const int hw0 = pbase & 65535;
    for (int i = tid; i < 2048; i += 256) {
        int o = i & 63, c = i >> 6;
        ws[i] = w[o * 32 + c];
    }
    for (int i = tid; i < 4096; i += 256) {
        int p = i & 127, c = i >> 7;
        xs[i] = x[(size_t)(b * 32 + c) * 65536 + hw0 + p];
    }
    __syncthreads();
    const int p = tid & 127, half = tid >> 7;
    u64t acc2[16];
#pragma unroll
    for (int q = 0; q < 16; q++) acc2[q] = 0ull;
#pragma unroll 4
    for (int c = 0; c < 32; c++) {
        float xv = xs[(c << 7) + p];
        u64t xv2; PACK2(xv2, xv, xv);
        const ulonglong2* wp = (const ulonglong2*)(ws + (c << 6) + (half << 5));
#pragma unroll
        for (int q = 0; q < 8; q++) {
            ulonglong2 wv = wp[q];
            FMA2(acc2[2 * q + 0], xv2, wv.x, acc2[2 * q + 0]);
            FMA2(acc2[2 * q + 1], xv2, wv.y, acc2[2 * q + 1]);
        }
    }
    float* op = g_xi + (size_t)(b * 64 + half * 32) * 65536 + hw0 + p;
#pragma unroll
    for (int q = 0; q < 16; q++) {
        float a0, a1;
        UNPACK2(a0, a1, acc2[q]);
        op[(size_t)(2 * q + 0) * 65536] = a0;
        op[(size_t)(2 * q + 1) * 65536] = a1;
    }
}

// ---------------------------------------------------------------------------
// K2: invo1 kernel map: avgpool2x2(x) -> 32->32 -> bn(1e-5)+relu -> 32->9
// ---------------------------------------------------------------------------
__global__ __launch_bounds__(256) void k_kgen1(const float* __restrict__ x,
                                               const float* __restrict__ wred,
                                               const float* __restrict__ sg,
                                               const float* __restrict__ sb,
                                               const float* __restrict__ sm,
                                               const float* __restrict__ sv,
                                               const float* __restrict__ wspan) {
    __shared__ float wr[32 * 32];
    __shared__ float wsp[9 * 32];
    __shared__ float ssc[32], sbi[32];
    for (int i = threadIdx.x; i < 1024; i += 256) {
        int o = i & 31, c = i >> 5;
        wr[i] = wred[o * 32 + c];
    }
    for (int i = threadIdx.x; i < 288; i += 256) wsp[i] = wspan[i];
    if (threadIdx.x < 32) {
        int o = threadIdx.x;
        float s = sg[o] * rsqrtf(sv[o] + 1e-5f);
        ssc[o] = s;
        sbi[o] = sb[o] - sm[o] * s;
    }
    __syncthreads();
    int p = blockIdx.x * 256 + threadIdx.x;
    int w = p & 127, h = (p >> 7) & 127, b = p >> 14;
    const float* xp = x + (size_t)b * 32 * 65536 + (h * 2) * 256 + (w * 2);
    u64t t2[16];
#pragma unroll
    for (int q = 0; q < 16; q++) t2[q] = 0ull;
#pragma unroll 4
    for (int c = 0; c < 32; c++) {
        const float* q = xp + (size_t)c * 65536;
        float pv = 0.25f * (q[0] + q[1] + q[256] + q[257]);
        u64t pv2; PACK2(pv2, pv, pv);
        const ulonglong2* wp = (const ulonglong2*)(wr + c * 32);
#pragma unroll
        for (int q4 = 0; q4 < 8; q4++) {   // 8 x ulonglong2 = 32 floats (FIXED)
            ulonglong2 wv = wp[q4];
            FMA2(t2[2 * q4 + 0], pv2, wv.x, t2[2 * q4 + 0]);
            FMA2(t2[2 * q4 + 1], pv2, wv.y, t2[2 * q4 + 1]);
        }
    }
    float tt[32];
#pragma unroll
    for (int q = 0; q < 16; q++) {
        float a0, a1;
        UNPACK2(a0, a1, t2[q]);
        tt[2 * q + 0] = a0;
        tt[2 * q + 1] = a1;
    }
#pragma unroll
    for (int o = 0; o < 32; o++) tt[o] = fmaxf(fmaf(tt[o], ssc[o], sbi[o]), 0.f);
    float* kp = g_kmap1 + (size_t)b * 9 * 16384 + (h << 7) + w;
#pragma unroll
    for (int j = 0; j < 9; j++) {
        float acc = 0.f;
#pragma unroll
        for (int o = 0; o < 32; o++) acc = fmaf(wsp[j * 32 + o], tt[o], acc);
        kp[(size_t)j * 16384] = acc;
    }
}

// ---------------------------------------------------------------------------
// K3: o1 = prelu(bn1(sum_k xi_patch * kmap1))  (stride 2, pad 1)
// ---------------------------------------------------------------------------
__global__ __launch_bounds__(256) void k_apply1(const float* __restrict__ bg,
                                                const float* __restrict__ bb,
                                                const float* __restrict__ bm,
                                                const float* __restrict__ bv,
                                                const float* __restrict__ pr1) {
    __shared__ float sc[64], bi[64], pr[64];
    if (threadIdx.x < 64) {
        int c = threadIdx.x;
        float s = bg[c] * rsqrtf(bv[c] + 1e-3f);
        sc[c] = s;
        bi[c] = bb[c] - bm[c] * s;
        pr[c] = pr1[c];
    }
    __syncthreads();
    int idx = blockIdx.x * 256 + threadIdx.x;
    int w = idx & 127, h = (idx >> 7) & 127, c4 = (idx >> 14) & 15, b = idx >> 18;
    const float* kp = g_kmap1 + (size_t)b * 9 * 16384 + (h << 7) + w;
    float kv[9];
    int roff[9];
    unsigned vmask = 0;
#pragma unroll
    for (int ki = 0; ki < 3; ki++) {
        int r = 2 * h - 1 + ki;
#pragma unroll
        for (int kj = 0; kj < 3; kj++) {
            int cc = 2 * w - 1 + kj;
            int k = ki * 3 + kj;
            kv[k] = kp[(size_t)k * 16384];
            bool ok = (r >= 0) && (cc >= 0);
            if (ok) vmask |= (1u << k);
            roff[k] = ok ? r * 256 + cc : 0;
        }
    }
#pragma unroll
    for (int q = 0; q < 4; q++) {
        int c = c4 * 4 + q;
        const float* xp = g_xi + ((size_t)b * 64 + c) * 65536;
        float acc = 0.f;
#pragma unroll
        for (int k = 0; k < 9; k++)
            if (vmask & (1u << k)) acc = fmaf(xp[roff[k]], kv[k], acc);
        float v = fmaf(acc, sc[c], bi[c]);
        g_o1[((size_t)(b * 64 + c) << 14) + (h << 7) + w] = v > 0.f ? v : pr[c] * v;
    }
}

// ---------------------------------------------------------------------------
// K4: block = (branch, row, batch), 256 threads = 128 px x 2 halves.
// f32x2 matvec+span; centers read directly from L2-resident g_o1.
// ---------------------------------------------------------------------------
__global__ __launch_bounds__(256) void k_dil(const float* __restrict__ wd_red,
                                             const float* __restrict__ sd_g,
                                             const float* __restrict__ sd_b,
                                             const float* __restrict__ sd_m,
                                             const float* __restrict__ sd_v,
                                             const float* __restrict__ wd_span,
                                             const float* __restrict__ bnd_g,
                                             const float* __restrict__ bnd_b,
                                             const float* __restrict__ bnd_m,
                                             const float* __restrict__ bnd_v,
                                             const float* __restrict__ prd,
                                             const float* __restrict__ bnf_g,
                                             const float* __restrict__ bnf_b,
                                             const float* __restrict__ bnf_m,
                                             const float* __restrict__ bnf_v,
                                             const float* __restrict__ prf,
                                             float* __restrict__ out) {
    __shared__ float wrT[64 * 64];    // wrT[c*64+o]
    __shared__ float wsp[9 * 64];
    __shared__ float part[2 * 9 * 128];
    __shared__ float ks[64], kb[64], os_[64], ob[64], opr[64], fs[64], fb[64], fpr[64];
    const int i = blockIdx.x;   // branch
    const int h = blockIdx.y;   // row
    const int b = blockIdx.z;   // batch
    const int tid = threadIdx.x;
    const int pix = tid & 127, half = tid >> 7;
    const float* base = g_o1 + ((size_t)b * 64 << 14);

    for (int t = tid; t < 4096; t += 256) {
        int o = t & 63, c = t >> 6;
        wrT[t] = wd_red[i * 4096 + o * 64 + c];
    }
    for (int t = tid; t < 576; t += 256) wsp[t] = wd_span[i * 576 + t];
    if (tid < 64) {
        int c = tid, g = i * 64 + c;
        float s1 = sd_g[g] * rsqrtf(sd_v[g] + 1e-5f);
        ks[c] = s1; kb[c] = sd_b[g] - sd_m[g] * s1;
        float s2 = bnd_g[g] * rsqrtf(bnd_v[g] + 1e-3f);
        os_[c] = s2; ob[c] = bnd_b[g] - bnd_m[g] * s2; opr[c] = prd[g];
        float s3 = bnf_g[g] * rsqrtf(bnf_v[g] + 1e-3f);
        fs[c] = s3; fb[c] = bnf_b[g] - bnf_m[g] * s3; fpr[c] = prf[g];
    }
    __syncthreads();

    // ---- 64x64 matvec, 32 outputs/thread as 16 f32x2 pairs ----
    const float* cen = base + (h << 7) + pix;
    u64t acc2[16];
#pragma unroll
    for (int q = 0; q < 16; q++) acc2[q] = 0ull;
#pragma unroll 4
    for (int c = 0; c < 64; c++) {
        float xc = __ldg(cen + ((size_t)c << 14));
        u64t xc2; PACK2(xc2, xc, xc);
        const ulonglong2* wp = (const ulonglong2*)(wrT + (c << 6) + (half << 5));
#pragma unroll
        for (int q = 0; q < 8; q++) {
            ulonglong2 wv = wp[q];
            FMA2(acc2[2 * q + 0], xc2, wv.x, acc2[2 * q + 0]);
            FMA2(acc2[2 * q + 1], xc2, wv.y, acc2[2 * q + 1]);
        }
    }
    // ---- bn(1e-5)+relu, repack ----
    u64t t2[16];
#pragma unroll
    for (int q = 0; q < 16; q++) {
        float a0, a1;
        UNPACK2(a0, a1, acc2[q]);
        int o = (half << 5) + 2 * q;
        float z0 = fmaxf(fmaf(a0, ks[o], kb[o]), 0.f);
        float z1 = fmaxf(fmaf(a1, ks[o + 1], kb[o + 1]), 0.f);
        PACK2(t2[q], z0, z1);
    }
    // ---- span partials (9 x 32 each half) ----
#pragma unroll
    for (int j = 0; j < 9; j++) {
        u64t s2 = 0ull;
        const u64t* wj = (const u64t*)(wsp + j * 64 + (half << 5));
#pragma unroll
        for (int q = 0; q < 16; q++) FMA2(s2, t2[q], wj[q], s2);
        float u0, u1;
        UNPACK2(u0, u1, s2);
        part[((half * 9 + j) << 7) + pix] = u0 + u1;
    }
    __syncthreads();
    float kk[9];
#pragma unroll
    for (int j = 0; j < 9; j++) kk[j] = part[(j << 7) + pix] + part[((9 + j) << 7) + pix];

    // ---- dilated 3x3 apply + fused epilogue (32 channels) ----
    const int dil = 1 << i;
    int offs[9];
    unsigned vmask = 0;
#pragma unroll
    for (int ki = 0; ki < 3; ki++) {
        int r = h + (ki - 1) * dil;
        bool rok = (unsigned)r < 128u;
#pragma unroll
        for (int kj = 0; kj < 3; kj++) {
            int cc = pix + (kj - 1) * dil;
            bool ok = rok && ((unsigned)cc < 128u);
            int k = ki * 3 + kj;
            if (ok) vmask |= (1u << k);
            offs[k] = ok ? (r << 7) + cc : 0;
        }
    }
    float* outp = out + ((size_t)(b * 320 + i * 64 + (half << 5)) << 14) + (h << 7) + pix;
#pragma unroll 2
    for (int cl = 0; cl < 32; cl++) {
        int c = (half << 5) + cl;
        const float* pc = base + ((size_t)c << 14);
        float a = 0.f;
#pragma unroll
        for (int k = 0; k < 9; k++)
            if (vmask & (1u << k)) a = fmaf(__ldg(pc + offs[k]), kk[k], a);
        float z = fmaf(a, os_[c], ob[c]);
        z = z > 0.f ? z : opr[c] * z;
        float y = fmaf(z, fs[c], fb[c]);
        outp[(size_t)cl << 14] = y > 0.f ? y : fpr[c] * y;
    }
}

// ---------------------------------------------------------------------------
extern "C" void kernel_launch(void* const* d_in, const int* in_sizes, int n_in,
                              void* d_out, int out_size) {
    const float* x       = (const float*)d_in[0];
    const float* w1_init = (const float*)d_in[1];
    const float* w1_red  = (const float*)d_in[2];
    const float* s1_g    = (const float*)d_in[3];
    const float* s1_b    = (const float*)d_in[4];
    const float* s1_m    = (const float*)d_in[5];
    const float* s1_v    = (const float*)d_in[6];
    const float* w1_span = (const float*)d_in[7];
    const float* bn1_g   = (const float*)d_in[8];
    const float* bn1_b   = (const float*)d_in[9];
    const float* bn1_m   = (const float*)d_in[10];
    const float* bn1_v   = (const float*)d_in[11];
    const float* pr1     = (const float*)d_in[12];
    const float* wd_red  = (const float*)d_in[13];
    const float* sd_g    = (const float*)d_in[14];
    const float* sd_b    = (const float*)d_in[15];
    const float* sd_m    = (const float*)d_in[16];
    const float* sd_v    = (const float*)d_in[17];
    const float* wd_span = (const float*)d_in[18];
    const float* bnd_g   = (const float*)d_in[19];
    const float* bnd_b   = (const float*)d_in[20];
    const float* bnd_m   = (const float*)d_in[21];
    const float* bnd_v   = (const float*)d_in[22];
    const float* prd     = (const float*)d_in[23];
    const float* bnf_g   = (const float*)d_in[24];
    const float* bnf_b   = (const float*)d_in[25];
    const float* bnf_m   = (const float*)d_in[26];
    const float* bnf_v   = (const float*)d_in[27];
    const float* prf     = (const float*)d_in[28];
    float* out = (float*)d_out;

    k_xi<<<4096, 256>>>(x, w1_init);
    k_kgen1<<<512, 256>>>(x, w1_red, s1_g, s1_b, s1_m, s1_v, w1_span);
    k_apply1<<<8192, 256>>>(bn1_g, bn1_b, bn1_m, bn1_v, pr1);
    k_dil<<<dim3(5, 128, 8), 256>>>(wd_red, sd_g, sd_b, sd_m, sd_v, wd_span,
                                    bnd_g, bnd_b, bnd_m, bnd_v, prd,
                                    bnf_g, bnf_b, bnf_m, bnf_v, prf, out);
}

// round 12
// speedup vs baseline: 1.6629x; 1.6629x over previous
#include <cuda_runtime.h>
#include <cstdint>

// ---------------------------------------------------------------------------
// DInPBlock: invo1 (32->64, s2) -> 5 dilated involutions -> concat -> bn+prelu
// Shapes: x (8,32,256,256) f32 ; out (8,320,128,128) f32
// ---------------------------------------------------------------------------

#define NBATCH 8

__device__ float g_xi[(size_t)NBATCH * 64 * 256 * 256];   // 134 MB
__device__ float g_kmap1[(size_t)NBATCH * 9 * 128 * 128];
__device__ float g_o1[(size_t)NBATCH * 64 * 128 * 128];   // 33.5 MB (L2-resident)

// ---------------------------------------------------------------------------
// K1: xi = conv1x1(x, w1_init)  (8,32,256,256) -> (8,64,256,256)
// 256 threads = 128 pixels x 2 halves; each thread 32 outputs; x row in smem
// ---------------------------------------------------------------------------
__global__ __launch_bounds__(256) void k_xi(const float* __restrict__ x,
                                            const float* __restrict__ w) {
    __shared__ float xs[32 * 128];  // xs[c*128+p]
    __shared__ float ws[32 * 64];   // ws[c*64+o] = w[o*32+c]
    const int tid = threadIdx.x;
    const int pbase = blockIdx.x * 128;
    const int b = pbase >> 16;
    const int hw0 = pbase & 65535;
    for (int i = tid; i < 2048; i += 256) {
        int o = i & 63, c = i >> 6;
        ws[i] = w[o * 32 + c];
    }
    for (int i = tid; i < 4096; i += 256) {
        int p = i & 127, c = i >> 7;
        xs[i] = x[(size_t)(b * 32 + c) * 65536 + hw0 + p];
    }
    __syncthreads();
    const int p = tid & 127, half = tid >> 7;
    float acc[32];
#pragma unroll
    for (int o = 0; o < 32; o++) acc[o] = 0.f;
#pragma unroll 4
    for (int c = 0; c < 32; c++) {
        float xv = xs[(c << 7) + p];
        const float4* wp = (const float4*)(ws + (c << 6) + (half << 5));
#pragma unroll
        for (int o4 = 0; o4 < 8; o4++) {
            float4 wv = wp[o4];
            acc[4 * o4 + 0] = fmaf(xv, wv.x, acc[4 * o4 + 0]);
            acc[4 * o4 + 1] = fmaf(xv, wv.y, acc[4 * o4 + 1]);
            acc[4 * o4 + 2] = fmaf(xv, wv.z, acc[4 * o4 + 2]);
            acc[4 * o4 + 3] = fmaf(xv, wv.w, acc[4 * o4 + 3]);
        }
    }
    float* op = g_xi + (size_t)(b * 64 + half * 32) * 65536 + hw0 + p;
#pragma unroll
    for (int o = 0; o < 32; o++) op[(size_t)o * 65536] = acc[o];
}

// ---------------------------------------------------------------------------
// K2: invo1 kernel map: avgpool2x2(x) -> 32->32 -> bn(1e-5)+relu -> 32->9
// ---------------------------------------------------------------------------
__global__ __launch_bounds__(256) void k_kgen1(const float* __restrict__ x,
                                               const float* __restrict__ wred,
                                               const float* __restrict__ sg,
                                               const float* __restrict__ sb,
                                               const float* __restrict__ sm,
                                               const float* __restrict__ sv,
                                               const float* __restrict__ wspan) {
    __shared__ float wr[32 * 32];
    __shared__ float wsp[9 * 32];
    __shared__ float ssc[32], sbi[32];
    for (int i = threadIdx.x; i < 1024; i += 256) {
        int o = i & 31, c = i >> 5;
        wr[i] = wred[o * 32 + c];
    }
    for (int i = threadIdx.x; i < 288; i += 256) wsp[i] = wspan[i];
    if (threadIdx.x < 32) {
        int o = threadIdx.x;
        float s = sg[o] * rsqrtf(sv[o] + 1e-5f);
        ssc[o] = s;
        sbi[o] = sb[o] - sm[o] * s;
    }
    __syncthreads();
    int p = blockIdx.x * 256 + threadIdx.x;
    int w = p & 127, h = (p >> 7) & 127, b = p >> 14;
    const float* xp = x + (size_t)b * 32 * 65536 + (h * 2) * 256 + (w * 2);
    float t[32];
#pragma unroll
    for (int o = 0; o < 32; o++) t[o] = 0.f;
#pragma unroll 4
    for (int c = 0; c < 32; c++) {
        const float* q = xp + (size_t)c * 65536;
        float pv = 0.25f * (q[0] + q[1] + q[256] + q[257]);
        const float4* wp = (const float4*)(wr + c * 32);
#pragma unroll
        for (int o4 = 0; o4 < 8; o4++) {
            float4 wv = wp[o4];
            t[4 * o4 + 0] = fmaf(pv, wv.x, t[4 * o4 + 0]);
            t[4 * o4 + 1] = fmaf(pv, wv.y, t[4 * o4 + 1]);
            t[4 * o4 + 2] = fmaf(pv, wv.z, t[4 * o4 + 2]);
            t[4 * o4 + 3] = fmaf(pv, wv.w, t[4 * o4 + 3]);
        }
    }
#pragma unroll
    for (int o = 0; o < 32; o++) t[o] = fmaxf(fmaf(t[o], ssc[o], sbi[o]), 0.f);
    float* kp = g_kmap1 + (size_t)b * 9 * 16384 + (h << 7) + w;
#pragma unroll
    for (int j = 0; j < 9; j++) {
        float acc = 0.f;
#pragma unroll
        for (int o = 0; o < 32; o++) acc = fmaf(wsp[j * 32 + o], t[o], acc);
        kp[(size_t)j * 16384] = acc;
    }
}

// ---------------------------------------------------------------------------
// K3: o1 = prelu(bn1(sum_k xi_patch * kmap1))  (stride 2, pad 1)
// ---------------------------------------------------------------------------
__global__ __launch_bounds__(256) void k_apply1(const float* __restrict__ bg,
                                                const float* __restrict__ bb,
                                                const float* __restrict__ bm,
                                                const float* __restrict__ bv,
                                                const float* __restrict__ pr1) {
    __shared__ float sc[64], bi[64], pr[64];
    if (threadIdx.x < 64) {
        int c = threadIdx.x;
        float s = bg[c] * rsqrtf(bv[c] + 1e-3f);
        sc[c] = s;
        bi[c] = bb[c] - bm[c] * s;
        pr[c] = pr1[c];
    }
    __syncthreads();
    int idx = blockIdx.x * 256 + threadIdx.x;
    int w = idx & 127, h = (idx >> 7) & 127, c4 = (idx >> 14) & 15, b = idx >> 18;
    const float* kp = g_kmap1 + (size_t)b * 9 * 16384 + (h << 7) + w;
    float kv[9];
    int roff[9];
    unsigned vmask = 0;
#pragma unroll
    for (int ki = 0; ki < 3; ki++) {
        int r = 2 * h - 1 + ki;
#pragma unroll
        for (int kj = 0; kj < 3; kj++) {
            int cc = 2 * w - 1 + kj;
            int k = ki * 3 + kj;
            kv[k] = kp[(size_t)k * 16384];
            bool ok = (r >= 0) && (cc >= 0);
            if (ok) vmask |= (1u << k);
            roff[k] = ok ? r * 256 + cc : 0;
        }
    }
#pragma unroll
    for (int q = 0; q < 4; q++) {
        int c = c4 * 4 + q;
        const float* xp = g_xi + ((size_t)b * 64 + c) * 65536;
        float acc = 0.f;
#pragma unroll
        for (int k = 0; k < 9; k++)
            if (vmask & (1u << k)) acc = fmaf(xp[roff[k]], kv[k], acc);
        float v = fmaf(acc, sc[c], bi[c]);
        g_o1[((size_t)(b * 64 + c) << 14) + (h << 7) + w] = v > 0.f ? v : pr[c] * v;
    }
}

// ---------------------------------------------------------------------------
// K4: block = (branch, row, batch). 256 threads = 4 quarters x 64 pixel-cols.
// Each thread: 2 pixels (p, p+64) x 16 outputs. Center row staged in smem;
// middle-row gather taps also served from smem.
// ---------------------------------------------------------------------------
__global__ __launch_bounds__(256) void k_dil(const float* __restrict__ wd_red,
                                             const float* __restrict__ sd_g,
                                             const float* __restrict__ sd_b,
                                             const float* __restrict__ sd_m,
                                             const float* __restrict__ sd_v,
                                             const float* __restrict__ wd_span,
                                             const float* __restrict__ bnd_g,
                                             const float* __restrict__ bnd_b,
                                             const float* __restrict__ bnd_m,
                                             const float* __restrict__ bnd_v,
                                             const float* __restrict__ prd,
                                             const float* __restrict__ bnf_g,
                                             const float* __restrict__ bnf_b,
                                             const float* __restrict__ bnf_m,
                                             const float* __restrict__ bnf_v,
                                             const float* __restrict__ prf,
                                             float* __restrict__ out) {
    __shared__ float cs[64 * 128];    // center row: cs[c*128+p]  (32 KB)
    __shared__ float wrT[64 * 64];    // wrT[c*64+o]              (16 KB)
    __shared__ float wsp[9 * 64];
    __shared__ float part[4 * 9 * 128];   // span partials         (18 KB)
    __shared__ float ks[64], kb[64], os_[64], ob[64], opr[64], fs[64], fb[64], fpr[64];
    const int i = blockIdx.x;   // branch
    const int h = blockIdx.y;   // row
    const int b = blockIdx.z;   // batch
    const int tid = threadIdx.x;
    const int q = tid >> 6;         // output quarter 0..3 (uniform per warp)
    const int p = tid & 63;         // pixel column 0..63
    const float* base = g_o1 + ((size_t)b * 64 << 14);

    for (int t = tid; t < 8192; t += 256) {
        int c = t >> 7, pc = t & 127;
        cs[t] = base[(c << 14) + (h << 7) + pc];
    }
    for (int t = tid; t < 4096; t += 256) {
        int o = t & 63, c = t >> 6;
        wrT[t] = wd_red[i * 4096 + o * 64 + c];
    }
    for (int t = tid; t < 576; t += 256) wsp[t] = wd_span[i * 576 + t];
    if (tid < 64) {
        int c = tid, g = i * 64 + c;
        float s1 = sd_g[g] * rsqrtf(sd_v[g] + 1e-5f);
        ks[c] = s1; kb[c] = sd_b[g] - sd_m[g] * s1;
        float s2 = bnd_g[g] * rsqrtf(bnd_v[g] + 1e-3f);
        os_[c] = s2; ob[c] = bnd_b[g] - bnd_m[g] * s2; opr[c] = prd[g];
        float s3 = bnf_g[g] * rsqrtf(bnf_v[g] + 1e-3f);
        fs[c] = s3; fb[c] = bnf_b[g] - bnf_m[g] * s3; fpr[c] = prf[g];
    }
    __syncthreads();

    // ---- 64x64 matvec: 2 pixels x 16 outputs per thread ----
    float acc0[16], acc1[16];
#pragma unroll
    for (int l = 0; l < 16; l++) { acc0[l] = 0.f; acc1[l] = 0.f; }
#pragma unroll 4
    for (int c = 0; c < 64; c++) {
        float xc0 = cs[(c << 7) + p];
        float xc1 = cs[(c << 7) + 64 + p];
        const float4* wp = (const float4*)(wrT + (c << 6) + (q << 4));
#pragma unroll
        for (int w4 = 0; w4 < 4; w4++) {
            float4 wv = wp[w4];
            acc0[4 * w4 + 0] = fmaf(xc0, wv.x, acc0[4 * w4 + 0]);
            acc0[4 * w4 + 1] = fmaf(xc0, wv.y, acc0[4 * w4 + 1]);
            acc0[4 * w4 + 2] = fmaf(xc0, wv.z, acc0[4 * w4 + 2]);
            acc0[4 * w4 + 3] = fmaf(xc0, wv.w, acc0[4 * w4 + 3]);
            acc1[4 * w4 + 0] = fmaf(xc1, wv.x, acc1[4 * w4 + 0]);
            acc1[4 * w4 + 1] = fmaf(xc1, wv.y, acc1[4 * w4 + 1]);
            acc1[4 * w4 + 2] = fmaf(xc1, wv.z, acc1[4 * w4 + 2]);
            acc1[4 * w4 + 3] = fmaf(xc1, wv.w, acc1[4 * w4 + 3]);
        }
    }
    // ---- bn(1e-5)+relu in place ----
#pragma unroll
    for (int l = 0; l < 16; l++) {
        int o = (q << 4) + l;
        acc0[l] = fmaxf(fmaf(acc0[l], ks[o], kb[o]), 0.f);
        acc1[l] = fmaxf(fmaf(acc1[l], ks[o], kb[o]), 0.f);
    }
    // ---- span partials: part[q][j][pix] ----
#pragma unroll
    for (int j = 0; j < 9; j++) {
        float s0 = 0.f, s1 = 0.f;
        const float* wj = wsp + j * 64 + (q << 4);
#pragma unroll
        for (int l = 0; l < 16; l++) {
            s0 = fmaf(wj[l], acc0[l], s0);
            s1 = fmaf(wj[l], acc1[l], s1);
        }
        part[((q * 9 + j) << 7) + p]      = s0;
        part[((q * 9 + j) << 7) + 64 + p] = s1;
    }
    __syncthreads();

    // ---- dilated 3x3 apply + fused epilogue, per pixel ----
    const int dil = 1 << i;
#pragma unroll 1
    for (int px = 0; px < 2; px++) {
        const int pp = p + (px << 6);
        float kkv[9];
#pragma unroll
        for (int j = 0; j < 9; j++)
            kkv[j] = part[(j << 7) + pp] + part[((9 + j) << 7) + pp] +
                     part[((18 + j) << 7) + pp] + part[((27 + j) << 7) + pp];
        int offs[9];
        unsigned vmask = 0;
#pragma unroll
        for (int ki = 0; ki < 3; ki++) {
            int r = h + (ki - 1) * dil;
            bool rok = (unsigned)r < 128u;
#pragma unroll
            for (int kj = 0; kj < 3; kj++) {
                int cc = pp + (kj - 1) * dil;
                bool ok = rok && ((unsigned)cc < 128u);
                int k = ki * 3 + kj;
                if (ok) vmask |= (1u << k);
                offs[k] = ok ? (r << 7) + cc : 0;
            }
        }
        float* outp = out + ((size_t)(b * 320 + i * 64 + (q << 4)) << 14) + (h << 7) + pp;
#pragma unroll 2
        for (int cl = 0; cl < 16; cl++) {
            int c = (q << 4) + cl;
            const float* pc = base + ((size_t)c << 14);
            float a = 0.f;
            // top & bottom rows from gmem (L2-resident)
#pragma unroll
            for (int k = 0; k < 3; k++)
                if (vmask & (1u << k)) a = fmaf(__ldg(pc + offs[k]), kkv[k], a);
#pragma unroll
            for (int k = 6; k < 9; k++)
                if (vmask & (1u << k)) a = fmaf(__ldg(pc + offs[k]), kkv[k], a);
            // middle row from smem (cs holds row h)
#pragma unroll
            for (int kj = 0; kj < 3; kj++) {
                int k = 3 + kj;
                if (vmask & (1u << k)) a = fmaf(cs[(c << 7) + pp + (kj - 1) * dil], kkv[k], a);
            }
            float z = fmaf(a, os_[c], ob[c]);
            z = z > 0.f ? z : opr[c] * z;
            float y = fmaf(z, fs[c], fb[c]);
            outp[(size_t)cl << 14] = y > 0.f ? y : fpr[c] * y;
        }
    }
}

// ---------------------------------------------------------------------------
extern "C" void kernel_launch(void* const* d_in, const int* in_sizes, int n_in,
                              void* d_out, int out_size) {
    const float* x       = (const float*)d_in[0];
    const float* w1_init = (const float*)d_in[1];
    const float* w1_red  = (const float*)d_in[2];
    const float* s1_g    = (const float*)d_in[3];
    const float* s1_b    = (const float*)d_in[4];
    const float* s1_m    = (const float*)d_in[5];
    const float* s1_v    = (const float*)d_in[6];
    const float* w1_span = (const float*)d_in[7];
    const float* bn1_g   = (const float*)d_in[8];
    const float* bn1_b   = (const float*)d_in[9];
    const float* bn1_m   = (const float*)d_in[10];
    const float* bn1_v   = (const float*)d_in[11];
    const float* pr1     = (const float*)d_in[12];
    const float* wd_red  = (const float*)d_in[13];
    const float* sd_g    = (const float*)d_in[14];
    const float* sd_b    = (const float*)d_in[15];
    const float* sd_m    = (const float*)d_in[16];
    const float* sd_v    = (const float*)d_in[17];
    const float* wd_span = (const float*)d_in[18];
    const float* bnd_g   = (const float*)d_in[19];
    const float* bnd_b   = (const float*)d_in[20];
    const float* bnd_m   = (const float*)d_in[21];
    const float* bnd_v   = (const float*)d_in[22];
    const float* prd     = (const float*)d_in[23];
    const float* bnf_g   = (const float*)d_in[24];
    const float* bnf_b   = (const float*)d_in[25];
    const float* bnf_m   = (const float*)d_in[26];
    const float* bnf_v   = (const float*)d_in[27];
    const float* prf     = (const float*)d_in[28];
    float* out = (float*)d_out;

    k_xi<<<4096, 256>>>(x, w1_init);
    k_kgen1<<<512, 256>>>(x, w1_red, s1_g, s1_b, s1_m, s1_v, w1_span);
    k_apply1<<<8192, 256>>>(bn1_g, bn1_b, bn1_m, bn1_v, pr1);
    k_dil<<<dim3(5, 128, 8), 256>>>(wd_red, sd_g, sd_b, sd_m, sd_v, wd_span,
                                    bnd_g, bnd_b, bnd_m, bnd_v, prd,
                                    bnf_g, bnf_b, bnf_m, bnf_v, prf, out);
}

// round 13
// speedup vs baseline: 2.1441x; 1.2894x over previous
#include <cuda_runtime.h>
#include <cstdint>

// ---------------------------------------------------------------------------
// DInPBlock: invo1 (32->64, s2) -> 5 dilated involutions -> concat -> bn+prelu
// Shapes: x (8,32,256,256) f32 ; out (8,320,128,128) f32
//
// Key algebraic fusion: o1 = prelu(bn1( W1 @ (sum_k kmap_k * x[:,tap_k]) ))
// (involution scalar kernel commutes with the 1x1 conv) -> no xi scratch.
// ---------------------------------------------------------------------------

#define NBATCH 8

__device__ float g_o1[(size_t)NBATCH * 64 * 128 * 128];   // 33.5 MB (L2-resident)

// dynamic-smem float offsets for k_o1
#define XR   0        // x rows [3][32][256]           24576
#define PSM  24576    // pooled [32][128]               4096
#define TSM  28672    // t      [32][128]               4096
#define KKO  32768    // kk     [9][128]                1152
#define SSM  33920    // s      [32][128]               4096
#define W1T  38016    // w1T    [32][64]                2048
#define WRO  40064    // wr     [32][32]                1024
#define WSP  41088    // wsp    [9][32]                  288
#define SC1  41376
#define SB1  41408
#define BSC  41440
#define BSB  41504
#define BPR  41568
#define K_O1_FLOATS 41632   // 166528 bytes

// ---------------------------------------------------------------------------
// k_o1: fused kgen1 + (xi*patches) + bn1 + prelu -> g_o1
// block = (h, b); 512 threads = 4 quads x 128 px
// ---------------------------------------------------------------------------
__global__ __launch_bounds__(512) void k_o1(const float* __restrict__ x,
                                            const float* __restrict__ w1_init,
                                            const float* __restrict__ w1_red,
                                            const float* __restrict__ s1_g,
                                            const float* __restrict__ s1_b,
                                            const float* __restrict__ s1_m,
                                            const float* __restrict__ s1_v,
                                            const float* __restrict__ w1_span,
                                            const float* __restrict__ bn1_g,
                                            const float* __restrict__ bn1_b,
                                            const float* __restrict__ bn1_m,
                                            const float* __restrict__ bn1_v,
                                            const float* __restrict__ pr1) {
    extern __shared__ float sh[];
    const int h = blockIdx.x;      // output row 0..127
    const int b = blockIdx.y;      // batch
    const int tid = threadIdx.x;
    const int p = tid & 127;       // pixel col
    const int quad = tid >> 7;     // 0..3

    // ---- load weights / params ----
    for (int i = tid; i < 2048; i += 512) {
        int c = i >> 6, o = i & 63;
        sh[W1T + i] = w1_init[o * 32 + c];
    }
    for (int i = tid; i < 1024; i += 512) {
        int c = i >> 5, o = i & 31;
        sh[WRO + i] = w1_red[o * 32 + c];
    }
    if (tid < 288) sh[WSP + tid] = w1_span[tid];
    if (tid < 32) {
        int o = tid;
        float s = s1_g[o] * rsqrtf(s1_v[o] + 1e-5f);
        sh[SC1 + o] = s;
        sh[SB1 + o] = s1_b[o] - s1_m[o] * s;
    }
    if (tid >= 64 && tid < 128) {
        int c = tid - 64;
        float s = bn1_g[c] * rsqrtf(bn1_v[c] + 1e-3f);
        sh[BSC + c] = s;
        sh[BSB + c] = bn1_b[c] - bn1_m[c] * s;
        sh[BPR + c] = pr1[c];
    }

    // ---- stage 3 input rows (2h-1, 2h, 2h+1) x 32 ch x 256 ----
    const float* xb = x + (size_t)b * 32 * 65536;
#pragma unroll 1
    for (int i = tid; i < 6144; i += 512) {   // 6144 float4 = 3*32*64
        int rr = i / 2048;                    // 0..2
        int rem = i - rr * 2048;              // c*64 + v4
        int c = rem >> 6, v4 = rem & 63;
        int g = 2 * h - 1 + rr;
        float4 val = make_float4(0.f, 0.f, 0.f, 0.f);
        if (g >= 0)
            val = *(const float4*)(xb + ((size_t)c * 256 + g) * 256 + v4 * 4);
        *(float4*)(sh + XR + ((rr * 32 + c) << 8) + v4 * 4) = val;
    }
    __syncthreads();

    // ---- avgpool 2x2 (rows 2h,2h+1 = rr 1,2) ----
#pragma unroll
    for (int l = 0; l < 8; l++) {
        int c = quad * 8 + l;
        const float* r1 = sh + XR + ((32 + c) << 8);
        const float* r2 = sh + XR + ((64 + c) << 8);
        sh[PSM + (c << 7) + p] = 0.25f * (r1[2 * p] + r1[2 * p + 1] + r2[2 * p] + r2[2 * p + 1]);
    }
    __syncthreads();

    // ---- t = relu(bn1e-5(wr @ pooled)) : quad computes 8 of 32 outputs ----
#pragma unroll
    for (int l = 0; l < 8; l++) {
        int o = quad * 8 + l;
        float acc = 0.f;
#pragma unroll
        for (int c = 0; c < 32; c++)
            acc = fmaf(sh[WRO + (c << 5) + o], sh[PSM + (c << 7) + p], acc);
        sh[TSM + (o << 7) + p] = fmaxf(fmaf(acc, sh[SC1 + o], sh[SB1 + o]), 0.f);
    }
    __syncthreads();

    // ---- kk = wsp @ t : quads 0..2 compute 3 j's each ----
    if (quad < 3) {
#pragma unroll
        for (int jj = 0; jj < 3; jj++) {
            int j = quad * 3 + jj;
            float acc = 0.f;
#pragma unroll
            for (int o = 0; o < 32; o++)
                acc = fmaf(sh[WSP + j * 32 + o], sh[TSM + (o << 7) + p], acc);
            sh[KKO + (j << 7) + p] = acc;
        }
    }
    __syncthreads();

    // ---- s[c] = sum_k kk_k * x[c, tap_k]  (taps in xr smem) ----
    {
        float kkr[9];
#pragma unroll
        for (int k = 0; k < 9; k++) kkr[k] = sh[KKO + (k << 7) + p];
#pragma unroll
        for (int l = 0; l < 8; l++) {
            int c = quad * 8 + l;
            float acc = 0.f;
#pragma unroll
            for (int ki = 0; ki < 3; ki++) {
                const float* xr = sh + XR + (((ki * 32) + c) << 8);
#pragma unroll
                for (int kj = 0; kj < 3; kj++) {
                    int col = 2 * p - 1 + kj;
                    float v = (col >= 0) ? xr[col] : 0.f;
                    acc = fmaf(kkr[ki * 3 + kj], v, acc);
                }
            }
            sh[SSM + (c << 7) + p] = acc;
        }
    }
    __syncthreads();

    // ---- o1 = prelu(bn1(W1 @ s)) : quad computes 16 of 64 outputs ----
    float acc[16];
#pragma unroll
    for (int l = 0; l < 16; l++) acc[l] = 0.f;
#pragma unroll 4
    for (int c = 0; c < 32; c++) {
        float sv = sh[SSM + (c << 7) + p];
        const float4* wp = (const float4*)(sh + W1T + (c << 6) + (quad << 4));
#pragma unroll
        for (int w4 = 0; w4 < 4; w4++) {
            float4 wv = wp[w4];
            acc[4 * w4 + 0] = fmaf(sv, wv.x, acc[4 * w4 + 0]);
            acc[4 * w4 + 1] = fmaf(sv, wv.y, acc[4 * w4 + 1]);
            acc[4 * w4 + 2] = fmaf(sv, wv.z, acc[4 * w4 + 2]);
            acc[4 * w4 + 3] = fmaf(sv, wv.w, acc[4 * w4 + 3]);
        }
    }
    float* op = g_o1 + ((size_t)(b * 64 + (quad << 4)) << 14) + (h << 7) + p;
#pragma unroll
    for (int l = 0; l < 16; l++) {
        int c = (quad << 4) + l;
        float v = fmaf(acc[l], sh[BSC + c], sh[BSB + c]);
        op[(size_t)l << 14] = v > 0.f ? v : sh[BPR + c] * v;
    }
}

// ---------------------------------------------------------------------------
// K4 (unchanged from R12 winner): block = (branch,row,batch), 256 thr =
// 4 quarters x 64 px-cols; 2 px x 16 outputs per thread.
// ---------------------------------------------------------------------------
__global__ __launch_bounds__(256) void k_dil(const float* __restrict__ wd_red,
                                             const float* __restrict__ sd_g,
                                             const float* __restrict__ sd_b,
                                             const float* __restrict__ sd_m,
                                             const float* __restrict__ sd_v,
                                             const float* __restrict__ wd_span,
                                             const float* __restrict__ bnd_g,
                                             const float* __restrict__ bnd_b,
                                             const float* __restrict__ bnd_m,
                                             const float* __restrict__ bnd_v,
                                             const float* __restrict__ prd,
                                             const float* __restrict__ bnf_g,
                                             const float* __restrict__ bnf_b,
                                             const float* __restrict__ bnf_m,
                                             const float* __restrict__ bnf_v,
                                             const float* __restrict__ prf,
                                             float* __restrict__ out) {
    __shared__ float cs[64 * 128];
    __shared__ float wrT[64 * 64];
    __shared__ float wsp[9 * 64];
    __shared__ float part[4 * 9 * 128];
    __shared__ float ks[64], kb[64], os_[64], ob[64], opr[64], fs[64], fb[64], fpr[64];
    const int i = blockIdx.x;
    const int h = blockIdx.y;
    const int b = blockIdx.z;
    const int tid = threadIdx.x;
    const int q = tid >> 6;
    const int p = tid & 63;
    const float* base = g_o1 + ((size_t)b * 64 << 14);

    for (int t = tid; t < 8192; t += 256) {
        int c = t >> 7, pc = t & 127;
        cs[t] = base[(c << 14) + (h << 7) + pc];
    }
    for (int t = tid; t < 4096; t += 256) {
        int o = t & 63, c = t >> 6;
        wrT[t] = wd_red[i * 4096 + o * 64 + c];
    }
    for (int t = tid; t < 576; t += 256) wsp[t] = wd_span[i * 576 + t];
    if (tid < 64) {
        int c = tid, g = i * 64 + c;
        float s1 = sd_g[g] * rsqrtf(sd_v[g] + 1e-5f);
        ks[c] = s1; kb[c] = sd_b[g] - sd_m[g] * s1;
        float s2 = bnd_g[g] * rsqrtf(bnd_v[g] + 1e-3f);
        os_[c] = s2; ob[c] = bnd_b[g] - bnd_m[g] * s2; opr[c] = prd[g];
        float s3 = bnf_g[g] * rsqrtf(bnf_v[g] + 1e-3f);
        fs[c] = s3; fb[c] = bnf_b[g] - bnf_m[g] * s3; fpr[c] = prf[g];
    }
    __syncthreads();

    float acc0[16], acc1[16];
#pragma unroll
    for (int l = 0; l < 16; l++) { acc0[l] = 0.f; acc1[l] = 0.f; }
#pragma unroll 4
    for (int c = 0; c < 64; c++) {
        float xc0 = cs[(c << 7) + p];
        float xc1 = cs[(c << 7) + 64 + p];
        const float4* wp = (const float4*)(wrT + (c << 6) + (q << 4));
#pragma unroll
        for (int w4 = 0; w4 < 4; w4++) {
            float4 wv = wp[w4];
            acc0[4 * w4 + 0] = fmaf(xc0, wv.x, acc0[4 * w4 + 0]);
            acc0[4 * w4 + 1] = fmaf(xc0, wv.y, acc0[4 * w4 + 1]);
            acc0[4 * w4 + 2] = fmaf(xc0, wv.z, acc0[4 * w4 + 2]);
            acc0[4 * w4 + 3] = fmaf(xc0, wv.w, acc0[4 * w4 + 3]);
            acc1[4 * w4 + 0] = fmaf(xc1, wv.x, acc1[4 * w4 + 0]);
            acc1[4 * w4 + 1] = fmaf(xc1, wv.y, acc1[4 * w4 + 1]);
            acc1[4 * w4 + 2] = fmaf(xc1, wv.z, acc1[4 * w4 + 2]);
            acc1[4 * w4 + 3] = fmaf(xc1, wv.w, acc1[4 * w4 + 3]);
        }
    }
#pragma unroll
    for (int l = 0; l < 16; l++) {
        int o = (q << 4) + l;
        acc0[l] = fmaxf(fmaf(acc0[l], ks[o], kb[o]), 0.f);
        acc1[l] = fmaxf(fmaf(acc1[l], ks[o], kb[o]), 0.f);
    }
#pragma unroll
    for (int j = 0; j < 9; j++) {
        float s0 = 0.f, s1 = 0.f;
        const float* wj = wsp + j * 64 + (q << 4);
#pragma unroll
        for (int l = 0; l < 16; l++) {
            s0 = fmaf(wj[l], acc0[l], s0);
            s1 = fmaf(wj[l], acc1[l], s1);
        }
        part[((q * 9 + j) << 7) + p]      = s0;
        part[((q * 9 + j) << 7) + 64 + p] = s1;
    }
    __syncthreads();

    const int dil = 1 << i;
#pragma unroll 1
    for (int px = 0; px < 2; px++) {
        const int pp = p + (px << 6);
        float kkv[9];
#pragma unroll
        for (int j = 0; j < 9; j++)
            kkv[j] = part[(j << 7) + pp] + part[((9 + j) << 7) + pp] +
                     part[((18 + j) << 7) + pp] + part[((27 + j) << 7) + pp];
        int offs[9];
        unsigned vmask = 0;
#pragma unroll
        for (int ki = 0; ki < 3; ki++) {
            int r = h + (ki - 1) * dil;
            bool rok = (unsigned)r < 128u;
#pragma unroll
            for (int kj = 0; kj < 3; kj++) {
                int cc = pp + (kj - 1) * dil;
                bool ok = rok && ((unsigned)cc < 128u);
                int k = ki * 3 + kj;
                if (ok) vmask |= (1u << k);
                offs[k] = ok ? (r << 7) + cc : 0;
            }
        }
        float* outp = out + ((size_t)(b * 320 + i * 64 + (q << 4)) << 14) + (h << 7) + pp;
#pragma unroll 2
        for (int cl = 0; cl < 16; cl++) {
            int c = (q << 4) + cl;
            const float* pc = base + ((size_t)c << 14);
            float a = 0.f;
#pragma unroll
            for (int k = 0; k < 3; k++)
                if (vmask & (1u << k)) a = fmaf(__ldg(pc + offs[k]), kkv[k], a);
#pragma unroll
            for (int k = 6; k < 9; k++)
                if (vmask & (1u << k)) a = fmaf(__ldg(pc + offs[k]), kkv[k], a);
#pragma unroll
            for (int kj = 0; kj < 3; kj++) {
                int k = 3 + kj;
                if (vmask & (1u << k)) a = fmaf(cs[(c << 7) + pp + (kj - 1) * dil], kkv[k], a);
            }
            float z = fmaf(a, os_[c], ob[c]);
            z = z > 0.f ? z : opr[c] * z;
            float y = fmaf(z, fs[c], fb[c]);
            outp[(size_t)cl << 14] = y > 0.f ? y : fpr[c] * y;
        }
    }
}

// ---------------------------------------------------------------------------
extern "C" void kernel_launch(void* const* d_in, const int* in_sizes, int n_in,
                              void* d_out, int out_size) {
    const float* x       = (const float*)d_in[0];
    const float* w1_init = (const float*)d_in[1];
    const float* w1_red  = (const float*)d_in[2];
    const float* s1_g    = (const float*)d_in[3];
    const float* s1_b    = (const float*)d_in[4];
    const float* s1_m    = (const float*)d_in[5];
    const float* s1_v    = (const float*)d_in[6];
    const float* w1_span = (const float*)d_in[7];
    const float* bn1_g   = (const float*)d_in[8];
    const float* bn1_b   = (const float*)d_in[9];
    const float* bn1_m   = (const float*)d_in[10];
    const float* bn1_v   = (const float*)d_in[11];
    const float* pr1     = (const float*)d_in[12];
    const float* wd_red  = (const float*)d_in[13];
    const float* sd_g    = (const float*)d_in[14];
    const float* sd_b    = (const float*)d_in[15];
    const float* sd_m    = (const float*)d_in[16];
    const float* sd_v    = (const float*)d_in[17];
    const float* wd_span = (const float*)d_in[18];
    const float* bnd_g   = (const float*)d_in[19];
    const float* bnd_b   = (const float*)d_in[20];
    const float* bnd_m   = (const float*)d_in[21];
    const float* bnd_v   = (const float*)d_in[22];
    const float* prd     = (const float*)d_in[23];
    const float* bnf_g   = (const float*)d_in[24];
    const float* bnf_b   = (const float*)d_in[25];
    const float* bnf_m   = (const float*)d_in[26];
    const float* bnf_v   = (const float*)d_in[27];
    const float* prf     = (const float*)d_in[28];
    float* out = (float*)d_out;

    static int smem_set = 0;
    if (!smem_set) {
        cudaFuncSetAttribute(k_o1, cudaFuncAttributeMaxDynamicSharedMemorySize,
                             K_O1_FLOATS * 4);
        smem_set = 1;
    }

    k_o1<<<dim3(128, 8), 512, K_O1_FLOATS * 4>>>(
        x, w1_init, w1_red, s1_g, s1_b, s1_m, s1_v, w1_span,
        bn1_g, bn1_b, bn1_m, bn1_v, pr1);
    k_dil<<<dim3(5, 128, 8), 256>>>(wd_red, sd_g, sd_b, sd_m, sd_v, wd_span,
                                    bnd_g, bnd_b, bnd_m, bnd_v, prd,
                                    bnf_g, bnf_b, bnf_m, bnf_v, prf, out);
}